// round 3
// baseline (speedup 1.0000x reference)
#include <cuda_runtime.h>

// DelayBuffer: out[b, t, i*D + c] = emb[b, t - d_i, c] if t >= d_i else emb[b, t, c]
// d_i = (1, 2, 4, 8, 16, 32) = 1 << i
// B=4, S=4096, D=1024 (fp32). Output [B, S, 6*D].
//
// Pure streaming copy: one block (256 threads) writes one (b, t, delay)
// segment of 1024 floats as 256 float4s. Reads hit L2 after the first
// delay touches a line (input = 64 MiB < 126 MiB L2).

static constexpr int B = 4;
static constexpr int S = 4096;
static constexpr int D = 1024;
static constexpr int D4 = D / 4;       // 256 float4 per segment
static constexpr int ND = 6;           // number of delays

__global__ __launch_bounds__(D4, 8)
void delay_buffer_kernel(const float4* __restrict__ in, float4* __restrict__ out) {
    const int c4 = threadIdx.x;        // 0..255 within segment
    const int di = blockIdx.x;         // delay index 0..5
    const int t  = blockIdx.y;         // 0..4095
    const int b  = blockIdx.z;         // 0..3

    const int d = 1 << di;             // DELAYS = (1,2,4,8,16,32)
    const int src_t = (t >= d) ? (t - d) : t;

    // input row: (b*S + src_t) * D4 ; output: ((b*S + t)*ND + di) * D4
    const float4 v = in[(b * S + src_t) * D4 + c4];
    out[((b * S + t) * ND + di) * D4 + c4] = v;
}

extern "C" void kernel_launch(void* const* d_in, const int* in_sizes, int n_in,
                              void* d_out, int out_size) {
    const float4* in = (const float4*)d_in[0];
    float4* out = (float4*)d_out;

    dim3 grid(ND, S, B);
    delay_buffer_kernel<<<grid, D4>>>(in, out);
}

// round 4
// speedup vs baseline: 1.0007x; 1.0007x over previous
#include <cuda_runtime.h>

// DelayBuffer: out[b, t, i*D + c] = emb[b, t - d_i, c] if t >= d_i else emb[b, t, c]
// d_i = (1, 2, 4, 8, 16, 32) = 1 << i
// B=4, S=4096, D=1024 (fp32). Output [B, S, 6*D].
//
// Pure streaming copy: one block (256 threads) writes one (b, t, delay)
// segment of 1024 floats as 256 float4s. Reads hit L2 after the first
// delay touches a line (input = 64 MiB < 126 MiB L2).

static constexpr int B = 4;
static constexpr int S = 4096;
static constexpr int D = 1024;
static constexpr int D4 = D / 4;       // 256 float4 per segment
static constexpr int ND = 6;           // number of delays

__global__ __launch_bounds__(D4, 8)
void delay_buffer_kernel(const float4* __restrict__ in, float4* __restrict__ out) {
    const int c4 = threadIdx.x;        // 0..255 within segment
    const int di = blockIdx.x;         // delay index 0..5
    const int t  = blockIdx.y;         // 0..4095
    const int b  = blockIdx.z;         // 0..3

    const int d = 1 << di;             // DELAYS = (1,2,4,8,16,32)
    const int src_t = (t >= d) ? (t - d) : t;

    // input row: (b*S + src_t) * D4 ; output: ((b*S + t)*ND + di) * D4
    const float4 v = in[(b * S + src_t) * D4 + c4];
    out[((b * S + t) * ND + di) * D4 + c4] = v;
}

extern "C" void kernel_launch(void* const* d_in, const int* in_sizes, int n_in,
                              void* d_out, int out_size) {
    const float4* in = (const float4*)d_in[0];
    float4* out = (float4*)d_out;

    dim3 grid(ND, S, B);
    delay_buffer_kernel<<<grid, D4>>>(in, out);
}

// round 5
// speedup vs baseline: 1.2496x; 1.2487x over previous
#include <cuda_runtime.h>

// DelayBuffer: out[b, t, i*D + c] = emb[b, t - d_i, c] if t >= d_i else emb[b, t, c]
// d_i in (1, 2, 4, 8, 16, 32) = 1 << i
// B=4, S=4096, D=1024 (fp32). Output [B, S, 6*D].
//
// One block (256 threads) handles one (b, t): all 6 delay segments.
// Each thread issues 6 independent float4 loads (MLP=6, hides DRAM/L2
// latency), then 6 streaming float4 stores into the contiguous 24 KiB
// output row. Input (64 MiB) stays L2-resident; output (402 MiB) streams
// through with evict-first stores.

static constexpr int B  = 4;
static constexpr int S  = 4096;
static constexpr int D  = 1024;
static constexpr int D4 = D / 4;   // 256 float4 per segment
static constexpr int ND = 6;       // number of delays

__global__ __launch_bounds__(D4, 8)
void delay_buffer_kernel(const float4* __restrict__ in, float4* __restrict__ out) {
    const int c4 = threadIdx.x;    // 0..255 within a segment
    const int t  = blockIdx.x;     // 0..4095
    const int b  = blockIdx.y;     // 0..3

    const int row = b * S + t;

    // 6 independent loads, batched for MLP
    float4 v[ND];
#pragma unroll
    for (int i = 0; i < ND; i++) {
        const int d = 1 << i;                       // DELAYS = (1,2,4,8,16,32)
        const int src_t = (t >= d) ? (t - d) : t;
        v[i] = __ldg(&in[(b * S + src_t) * D4 + c4]);
    }

    // 6 streaming stores into contiguous output row [row, 6*D]
    float4* orow = out + (size_t)row * (ND * D4) + c4;
#pragma unroll
    for (int i = 0; i < ND; i++) {
        __stcs(orow + i * D4, v[i]);
    }
}

extern "C" void kernel_launch(void* const* d_in, const int* in_sizes, int n_in,
                              void* d_out, int out_size) {
    const float4* in = (const float4*)d_in[0];
    float4* out = (float4*)d_out;

    dim3 grid(S, B);
    delay_buffer_kernel<<<grid, D4>>>(in, out);
}

// round 6
// speedup vs baseline: 1.2501x; 1.0004x over previous
#include <cuda_runtime.h>

// DelayBuffer: out[b, t, i*D + c] = emb[b, t - d_i, c] if t >= d_i else emb[b, t, c]
// d_i in (1, 2, 4, 8, 16, 32) = 1 << i
// B=4, S=4096, D=1024 (fp32). Output [B, S, 6*D].
//
// One block (256 threads) handles one (b, t): all 6 delay segments.
// Each thread issues 6 independent float4 loads (MLP=6, hides DRAM/L2
// latency), then 6 streaming float4 stores into the contiguous 24 KiB
// output row. Input (64 MiB) stays L2-resident; output (402 MiB) streams
// through with evict-first stores.

static constexpr int B  = 4;
static constexpr int S  = 4096;
static constexpr int D  = 1024;
static constexpr int D4 = D / 4;   // 256 float4 per segment
static constexpr int ND = 6;       // number of delays

__global__ __launch_bounds__(D4, 8)
void delay_buffer_kernel(const float4* __restrict__ in, float4* __restrict__ out) {
    const int c4 = threadIdx.x;    // 0..255 within a segment
    const int t  = blockIdx.x;     // 0..4095
    const int b  = blockIdx.y;     // 0..3

    const int row = b * S + t;

    // 6 independent loads, batched for MLP
    float4 v[ND];
#pragma unroll
    for (int i = 0; i < ND; i++) {
        const int d = 1 << i;                       // DELAYS = (1,2,4,8,16,32)
        const int src_t = (t >= d) ? (t - d) : t;
        v[i] = __ldg(&in[(b * S + src_t) * D4 + c4]);
    }

    // 6 streaming stores into contiguous output row [row, 6*D]
    float4* orow = out + (size_t)row * (ND * D4) + c4;
#pragma unroll
    for (int i = 0; i < ND; i++) {
        __stcs(orow + i * D4, v[i]);
    }
}

extern "C" void kernel_launch(void* const* d_in, const int* in_sizes, int n_in,
                              void* d_out, int out_size) {
    const float4* in = (const float4*)d_in[0];
    float4* out = (float4*)d_out;

    dim3 grid(S, B);
    delay_buffer_kernel<<<grid, D4>>>(in, out);
}